// round 7
// baseline (speedup 1.0000x reference)
#include <cuda_runtime.h>
#include <math.h>
#include <stdint.h>

#define H    768
#define F    3072
#define E    8
#define NTOK 1024
#define CAP  1024
#define ROWS (E*CAP)
#define NSPLIT 3
#define KSPL (F / NSPLIT)   // 1024

// ---- scratch (static device globals; no runtime allocation) ----
__device__ int   g_cnt[E];
__device__ int   g_tok[ROWS];
__device__ float g_rw[ROWS];
__device__ int   g_slot_row[NTOK*2];
__device__ float g_xr[NTOK*H];             // tf32(RNA)-rounded x
__device__ float g_h[(size_t)ROWS * F];    // tf32-rounded gelu(x@w1)
__device__ float g_ys[NSPLIT][(size_t)ROWS * H];

// ---------------------------------------------------------------
__global__ void zero_cnt_kernel() {
    if (threadIdx.x < E) g_cnt[threadIdx.x] = 0;
}

__device__ __forceinline__ uint32_t f2tf32(float f) {
    uint32_t u;
    asm("cvt.rna.tf32.f32 %0, %1;" : "=r"(u) : "f"(f));
    return u;
}

// router + x pre-rounding fused (1 warp per token)
__global__ void router_kernel(const float* __restrict__ x,
                              const float* __restrict__ rw) {
    int warp = (blockIdx.x * blockDim.x + threadIdx.x) >> 5;
    int lane = threadIdx.x & 31;
    if (warp >= NTOK) return;
    const float* xr = x + warp * H;

    // pre-round this token's row into g_xr (float4 per lane, 6 iters)
    {
        const float4* src = (const float4*)xr;
        float4* dst = (float4*)(g_xr + warp * H);
#pragma unroll
        for (int i = lane; i < H / 4; i += 32) {
            float4 v = src[i];
            v.x = __uint_as_float(f2tf32(v.x));
            v.y = __uint_as_float(f2tf32(v.y));
            v.z = __uint_as_float(f2tf32(v.z));
            v.w = __uint_as_float(f2tf32(v.w));
            dst[i] = v;
        }
    }

    float acc[E];
#pragma unroll
    for (int e = 0; e < E; e++) acc[e] = 0.f;
    for (int k = lane; k < H; k += 32) {
        float xv = xr[k];
        const float* r = rw + k * E;
#pragma unroll
        for (int e = 0; e < E; e++) acc[e] += xv * r[e];
    }
#pragma unroll
    for (int e = 0; e < E; e++) {
#pragma unroll
        for (int o = 16; o > 0; o >>= 1)
            acc[e] += __shfl_down_sync(0xffffffffu, acc[e], o);
    }
    if (lane == 0) {
        float b0 = -INFINITY, b1 = -INFINITY;
        int i0 = 0, i1 = 0;
#pragma unroll
        for (int e = 0; e < E; e++) {
            float v = acc[e];
            if (v > b0) { b1 = b0; i1 = i0; b0 = v; i0 = e; }
            else if (v > b1) { b1 = v; i1 = e; }
        }
        float s  = expf(b1 - b0);
        float w0 = 1.f / (1.f + s);
        float w1 = s / (1.f + s);

        int p0 = atomicAdd(&g_cnt[i0], 1);
        int r0 = i0 * CAP + p0;
        g_tok[r0] = warp; g_rw[r0] = w0; g_slot_row[warp * 2 + 0] = r0;

        int p1 = atomicAdd(&g_cnt[i1], 1);
        int r1 = i1 * CAP + p1;
        g_tok[r1] = warp; g_rw[r1] = w1; g_slot_row[warp * 2 + 1] = r1;
    }
}

__device__ __forceinline__ float gelu_exact(float v) {
    return 0.5f * v * (1.0f + erff(v * 0.70710678118654752f));
}

__device__ __forceinline__ void mma_tf32(float c[4],
                                         uint32_t a0, uint32_t a1, uint32_t a2, uint32_t a3,
                                         uint32_t b0, uint32_t b1) {
    asm volatile(
        "mma.sync.aligned.m16n8k8.row.col.f32.tf32.tf32.f32 "
        "{%0,%1,%2,%3},{%4,%5,%6,%7},{%8,%9},{%0,%1,%2,%3};"
        : "+f"(c[0]), "+f"(c[1]), "+f"(c[2]), "+f"(c[3])
        : "r"(a0), "r"(a1), "r"(a2), "r"(a3), "r"(b0), "r"(b1));
}

#define CP_ASYNC16(dst, src) \
    asm volatile("cp.async.cg.shared.global [%0], [%1], 16;" :: "r"(dst), "l"(src))
#define CP_COMMIT() asm volatile("cp.async.commit_group;")
#define CP_WAIT0()  asm volatile("cp.async.wait_group 0;")
#define STS128U(a, x, y, z, w) \
    asm volatile("st.shared.v4.b32 [%0], {%1,%2,%3,%4};" :: "r"(a), "r"(x), "r"(y), "r"(z), "r"(w) : "memory")

// ---------------------------------------------------------------
// MODE 0: g_h = rna(gelu(g_xr[gather] @ w1))   KSTR=768,  KLEN=768,  ND=3072
// MODE 1: g_ys[spl] = g_h @ w2[kslice]         KSTR=3072, KLEN=1024, ND=768
// 128x128 tile, BK=16, double-buffered smem, cp.async A (pre-rounded),
// register-staged LDG+cvt+STS B, ONE __syncthreads per iter.
// 8 warps (2x4), warp = 64x32 via m16n8k8 tf32. No cvt in inner loop.
template<int KSTR, int KLEN, int ND, int MODE>
__global__ void __launch_bounds__(256, 2)
moe_mma_kernel(const float* __restrict__ Bw) {
    int e, spl;
    if (MODE == 0) { e = blockIdx.z; spl = 0; }
    else           { e = blockIdx.z / NSPLIT; spl = blockIdx.z % NSPLIT; }
    const int cnt = g_cnt[e];
    const int m0  = blockIdx.y * 128;
    if (m0 >= cnt) return;
    const int n0   = blockIdx.x * 128;
    const int kbeg = spl * KLEN;

    __shared__ float As[2][128][20];   // [m][k], pre-rounded tf32 bits as float
    __shared__ float Bs[2][16][136];   // [k][n], tf32 bits

    const int t    = threadIdx.x;
    const int warp = t >> 5, lane = t & 31;
    const int wr = warp >> 2, wc = warp & 3;
    const int g  = lane >> 2, tg = lane & 3;

    // ---- A: cp.async, thread t -> row m = t>>1, 8-float seg (t&1)*8 ----
    const int am = t >> 1;
    const int ak = (t & 1) * 8;
    const float* arow;
    if (MODE == 0) {
        int tok = (m0 + am < cnt) ? g_tok[e * CAP + m0 + am] : 0;
        arow = g_xr + (size_t)tok * KSTR;
    } else {
        int rr = e * CAP + ((m0 + am < cnt) ? m0 + am : 0);
        arow = g_h + (size_t)rr * KSTR + kbeg;
    }
    uint32_t dA[2][2];
#pragma unroll
    for (int s = 0; s < 2; s++) {
        dA[s][0] = (uint32_t)__cvta_generic_to_shared(&As[s][am][ak]);
        dA[s][1] = (uint32_t)__cvta_generic_to_shared(&As[s][am][ak + 4]);
    }

    // ---- B: LDG float4 x2 + cvt + STS, thread t -> k-row t>>4, cols (t&15)*8 ----
    const int bk = t >> 4;            // 0..15
    const int bc = (t & 15) * 8;      // 0..120
    const float* bptr = Bw + (size_t)e * KSTR * ND + (size_t)(kbeg + bk) * ND + n0 + bc;
    uint32_t dB[2][2];
#pragma unroll
    for (int s = 0; s < 2; s++) {
        dB[s][0] = (uint32_t)__cvta_generic_to_shared(&Bs[s][bk][bc]);
        dB[s][1] = (uint32_t)__cvta_generic_to_shared(&Bs[s][bk][bc + 4]);
    }

    float acc[4][4][4];
#pragma unroll
    for (int mt = 0; mt < 4; mt++)
#pragma unroll
        for (int nt = 0; nt < 4; nt++)
#pragma unroll
            for (int i = 0; i < 4; i++) acc[mt][nt][i] = 0.f;

    const int NIT = KLEN / 16;

    // prologue: A(0) via cp.async, B(0) into regs
    CP_ASYNC16(dA[0][0], arow + ak);
    CP_ASYNC16(dA[0][1], arow + ak + 4);
    CP_COMMIT();
    float4 b0v = *(const float4*)(bptr);
    float4 b1v = *(const float4*)(bptr + 4);

    for (int it = 0; it < NIT; it++) {
        const int s = it & 1;
        // stage B regs -> smem (convert to tf32 here, off the MMA chain)
        STS128U(dB[s][0], f2tf32(b0v.x), f2tf32(b0v.y), f2tf32(b0v.z), f2tf32(b0v.w));
        STS128U(dB[s][1], f2tf32(b1v.x), f2tf32(b1v.y), f2tf32(b1v.z), f2tf32(b1v.w));
        CP_WAIT0();
        __syncthreads();

        if (it + 1 < NIT) {
            const float* an = arow + (it + 1) * 16;
            CP_ASYNC16(dA[s ^ 1][0], an + ak);
            CP_ASYNC16(dA[s ^ 1][1], an + ak + 4);
            CP_COMMIT();
            const float* bn = bptr + (size_t)(it + 1) * 16 * ND;
            b0v = *(const float4*)(bn);
            b1v = *(const float4*)(bn + 4);
        }

#pragma unroll
        for (int kk = 0; kk < 2; kk++) {
            const int kb = kk * 8;
            uint32_t af[4][4];
#pragma unroll
            for (int mt = 0; mt < 4; mt++) {
                int rr = wr * 64 + mt * 16 + g;
                af[mt][0] = __float_as_uint(As[s][rr][kb + tg]);
                af[mt][1] = __float_as_uint(As[s][rr + 8][kb + tg]);
                af[mt][2] = __float_as_uint(As[s][rr][kb + tg + 4]);
                af[mt][3] = __float_as_uint(As[s][rr + 8][kb + tg + 4]);
            }
            uint32_t bf[4][2];
#pragma unroll
            for (int nt = 0; nt < 4; nt++) {
                int cc = wc * 32 + nt * 8 + g;
                bf[nt][0] = __float_as_uint(Bs[s][kb + tg][cc]);
                bf[nt][1] = __float_as_uint(Bs[s][kb + tg + 4][cc]);
            }
#pragma unroll
            for (int mt = 0; mt < 4; mt++)
#pragma unroll
                for (int nt = 0; nt < 4; nt++)
                    mma_tf32(acc[mt][nt], af[mt][0], af[mt][1], af[mt][2], af[mt][3],
                             bf[nt][0], bf[nt][1]);
        }
    }

    // ---- epilogue ----
#pragma unroll
    for (int mt = 0; mt < 4; mt++) {
        int rloc0 = m0 + wr * 64 + mt * 16 + g;
        int rloc1 = rloc0 + 8;
#pragma unroll
        for (int nt = 0; nt < 4; nt++) {
            int cc = n0 + wc * 32 + nt * 8 + tg * 2;
            if (MODE == 0) {
                if (rloc0 < cnt) {
                    float* p = g_h + (size_t)(e * CAP + rloc0) * ND + cc;
                    p[0] = __uint_as_float(f2tf32(gelu_exact(acc[mt][nt][0])));
                    p[1] = __uint_as_float(f2tf32(gelu_exact(acc[mt][nt][1])));
                }
                if (rloc1 < cnt) {
                    float* p = g_h + (size_t)(e * CAP + rloc1) * ND + cc;
                    p[0] = __uint_as_float(f2tf32(gelu_exact(acc[mt][nt][2])));
                    p[1] = __uint_as_float(f2tf32(gelu_exact(acc[mt][nt][3])));
                }
            } else {
                if (rloc0 < cnt) {
                    float* p = &g_ys[spl][(size_t)(e * CAP + rloc0) * ND + cc];
                    p[0] = acc[mt][nt][0];
                    p[1] = acc[mt][nt][1];
                }
                if (rloc1 < cnt) {
                    float* p = &g_ys[spl][(size_t)(e * CAP + rloc1) * ND + cc];
                    p[0] = acc[mt][nt][2];
                    p[1] = acc[mt][nt][3];
                }
            }
        }
    }
}

// ---------------------------------------------------------------
__global__ void combine_kernel(float* __restrict__ out) {
    int idx = blockIdx.x * blockDim.x + threadIdx.x;
    if (idx >= NTOK * H / 4) return;
    int elem = idx * 4;
    int n = elem / H;
    int h = elem % H;
    int r0 = g_slot_row[2 * n + 0];
    int r1 = g_slot_row[2 * n + 1];
    float gw0 = g_rw[r0], gw1 = g_rw[r1];

    float4 s0 = make_float4(0.f, 0.f, 0.f, 0.f);
    float4 s1 = make_float4(0.f, 0.f, 0.f, 0.f);
#pragma unroll
    for (int s = 0; s < NSPLIT; s++) {
        float4 a = *(const float4*)(&g_ys[s][0] + (size_t)r0 * H + h);
        float4 b = *(const float4*)(&g_ys[s][0] + (size_t)r1 * H + h);
        s0.x += a.x; s0.y += a.y; s0.z += a.z; s0.w += a.w;
        s1.x += b.x; s1.y += b.y; s1.z += b.z; s1.w += b.w;
    }
    float4 o;
    o.x = gw0 * s0.x + gw1 * s1.x;
    o.y = gw0 * s0.y + gw1 * s1.y;
    o.z = gw0 * s0.z + gw1 * s1.z;
    o.w = gw0 * s0.w + gw1 * s1.w;
    *(float4*)(out + elem) = o;
}

// ---------------------------------------------------------------
extern "C" void kernel_launch(void* const* d_in, const int* in_sizes, int n_in,
                              void* d_out, int out_size) {
    const float* x  = (const float*)d_in[0];
    const float* rw = (const float*)d_in[1];
    const float* w1 = (const float*)d_in[2];
    const float* w2 = (const float*)d_in[3];
    float* out = (float*)d_out;

    zero_cnt_kernel<<<1, 32>>>();
    router_kernel<<<NTOK / 8, 256>>>(x, rw);

    dim3 g1(F / 128, NTOK / 128, E);                 // (24, 8, 8)
    moe_mma_kernel<H, H, F, 0><<<g1, 256>>>(w1);

    dim3 g2(H / 128, NTOK / 128, E * NSPLIT);        // (6, 8, 24)
    moe_mma_kernel<F, KSPL, H, 1><<<g2, 256>>>(w2);

    combine_kernel<<<(NTOK * H / 4 + 255) / 256, 256>>>(out);
}

// round 8
// speedup vs baseline: 1.1442x; 1.1442x over previous
#include <cuda_runtime.h>
#include <math.h>
#include <stdint.h>

#define H    768
#define F    3072
#define E    8
#define NTOK 1024
#define CAP  1024
#define ROWS (E*CAP)
#define NSPLIT 3
#define KSPL (F / NSPLIT)   // 1024

// ---- scratch (static device globals; no runtime allocation) ----
__device__ int   g_cnt[E];
__device__ int   g_tok[ROWS];
__device__ float g_rw[ROWS];
__device__ int   g_slot_row[NTOK*2];
__device__ float g_xr[NTOK*H];             // tf32(RNA)-rounded x
__device__ float g_h[(size_t)ROWS * F];    // tf32-rounded gelu(x@w1)
__device__ float g_ys[NSPLIT][(size_t)ROWS * H];

// ---------------------------------------------------------------
__global__ void zero_cnt_kernel() {
    if (threadIdx.x < E) g_cnt[threadIdx.x] = 0;
}

__device__ __forceinline__ uint32_t f2tf32(float f) {
    uint32_t u;
    asm("cvt.rna.tf32.f32 %0, %1;" : "=r"(u) : "f"(f));
    return u;
}

// router + x pre-rounding fused (1 warp per token)
__global__ void router_kernel(const float* __restrict__ x,
                              const float* __restrict__ rw) {
    int warp = (blockIdx.x * blockDim.x + threadIdx.x) >> 5;
    int lane = threadIdx.x & 31;
    if (warp >= NTOK) return;
    const float* xr = x + warp * H;

    // pre-round this token's row into g_xr
    {
        const float4* src = (const float4*)xr;
        float4* dst = (float4*)(g_xr + warp * H);
#pragma unroll
        for (int i = lane; i < H / 4; i += 32) {
            float4 v = src[i];
            v.x = __uint_as_float(f2tf32(v.x));
            v.y = __uint_as_float(f2tf32(v.y));
            v.z = __uint_as_float(f2tf32(v.z));
            v.w = __uint_as_float(f2tf32(v.w));
            dst[i] = v;
        }
    }

    float acc[E];
#pragma unroll
    for (int e = 0; e < E; e++) acc[e] = 0.f;
    for (int k = lane; k < H; k += 32) {
        float xv = xr[k];
        const float* r = rw + k * E;
#pragma unroll
        for (int e = 0; e < E; e++) acc[e] += xv * r[e];
    }
#pragma unroll
    for (int e = 0; e < E; e++) {
#pragma unroll
        for (int o = 16; o > 0; o >>= 1)
            acc[e] += __shfl_down_sync(0xffffffffu, acc[e], o);
    }
    if (lane == 0) {
        float b0 = -INFINITY, b1 = -INFINITY;
        int i0 = 0, i1 = 0;
#pragma unroll
        for (int e = 0; e < E; e++) {
            float v = acc[e];
            if (v > b0) { b1 = b0; i1 = i0; b0 = v; i0 = e; }
            else if (v > b1) { b1 = v; i1 = e; }
        }
        float s  = expf(b1 - b0);
        float w0 = 1.f / (1.f + s);
        float w1 = s / (1.f + s);

        int p0 = atomicAdd(&g_cnt[i0], 1);
        int r0 = i0 * CAP + p0;
        g_tok[r0] = warp; g_rw[r0] = w0; g_slot_row[warp * 2 + 0] = r0;

        int p1 = atomicAdd(&g_cnt[i1], 1);
        int r1 = i1 * CAP + p1;
        g_tok[r1] = warp; g_rw[r1] = w1; g_slot_row[warp * 2 + 1] = r1;
    }
}

__device__ __forceinline__ float gelu_exact(float v) {
    return 0.5f * v * (1.0f + erff(v * 0.70710678118654752f));
}

__device__ __forceinline__ void mma_tf32(float c[4],
                                         uint32_t a0, uint32_t a1, uint32_t a2, uint32_t a3,
                                         uint32_t b0, uint32_t b1) {
    asm volatile(
        "mma.sync.aligned.m16n8k8.row.col.f32.tf32.tf32.f32 "
        "{%0,%1,%2,%3},{%4,%5,%6,%7},{%8,%9},{%0,%1,%2,%3};"
        : "+f"(c[0]), "+f"(c[1]), "+f"(c[2]), "+f"(c[3])
        : "r"(a0), "r"(a1), "r"(a2), "r"(a3), "r"(b0), "r"(b1));
}

#define CP_ASYNC16(dst, src) \
    asm volatile("cp.async.cg.shared.global [%0], [%1], 16;" :: "r"(dst), "l"(src))
#define CP_COMMIT() asm volatile("cp.async.commit_group;")
#define CP_WAIT(n)  asm volatile("cp.async.wait_group %0;" :: "n"(n))

// ---------------------------------------------------------------
// MODE 0: g_h = rna(gelu(g_xr[gather] @ w1))   KSTR=768,  KLEN=768,  ND=3072
// MODE 1: g_ys[spl] = g_h @ w2[kslice]         KSTR=3072, KLEN=1024, ND=768
// EXACT R4 pipeline (2-stage cp.async A+B, two barriers/iter).
// A is pre-rounded tf32 -> no cvt on A fragments; B cvt post-LDS only.
template<int KSTR, int KLEN, int ND, int MODE>
__global__ void __launch_bounds__(256, 2)
moe_mma_kernel(const float* __restrict__ Bw) {
    int e, spl;
    if (MODE == 0) { e = blockIdx.z; spl = 0; }
    else           { e = blockIdx.z / NSPLIT; spl = blockIdx.z % NSPLIT; }
    const int cnt = g_cnt[e];
    const int m0  = blockIdx.y * 128;
    if (m0 >= cnt) return;
    const int n0   = blockIdx.x * 128;
    const int kbeg = spl * KLEN;

    __shared__ float As[2][128][20];   // [m][k], pre-rounded
    __shared__ float Bs[2][16][136];   // [k][n], raw fp32

    const int t    = threadIdx.x;
    const int warp = t >> 5, lane = t & 31;
    const int wr = warp >> 2, wc = warp & 3;
    const int g  = lane >> 2, tg = lane & 3;

    // ---- global load mapping (R4) ----
    const int r0   = t >> 2;          // 0..63
    const int r1   = r0 + 64;
    const int segc = (t & 3) * 4;
    const float* aptr0;
    const float* aptr1;
    if (MODE == 0) {
        int ra = (m0 + r0 < cnt) ? g_tok[e * CAP + m0 + r0] : 0;
        int rb = (m0 + r1 < cnt) ? g_tok[e * CAP + m0 + r1] : 0;
        aptr0 = g_xr + (size_t)ra * KSTR + segc;
        aptr1 = g_xr + (size_t)rb * KSTR + segc;
    } else {
        int ra = e * CAP + ((m0 + r0 < cnt) ? m0 + r0 : 0);
        int rb = e * CAP + ((m0 + r1 < cnt) ? m0 + r1 : 0);
        aptr0 = g_h + (size_t)ra * KSTR + kbeg + segc;
        aptr1 = g_h + (size_t)rb * KSTR + kbeg + segc;
    }
    const int bk0  = t >> 5;
    const int bk1  = bk0 + 8;
    const int bseg = (t & 31) * 4;
    const float* bptr = Bw + (size_t)e * KSTR * ND + (size_t)kbeg * ND + n0 + bseg;

    uint32_t dA0[2], dA1[2], dB0[2], dB1[2];
#pragma unroll
    for (int s = 0; s < 2; s++) {
        dA0[s] = (uint32_t)__cvta_generic_to_shared(&As[s][r0][segc]);
        dA1[s] = (uint32_t)__cvta_generic_to_shared(&As[s][r1][segc]);
        dB0[s] = (uint32_t)__cvta_generic_to_shared(&Bs[s][bk0][bseg]);
        dB1[s] = (uint32_t)__cvta_generic_to_shared(&Bs[s][bk1][bseg]);
    }

#define LOAD_STAGE(s, k0)                                              \
    do {                                                               \
        CP_ASYNC16(dA0[s], aptr0 + (k0));                              \
        CP_ASYNC16(dA1[s], aptr1 + (k0));                              \
        CP_ASYNC16(dB0[s], bptr + (size_t)((k0) + bk0) * ND);          \
        CP_ASYNC16(dB1[s], bptr + (size_t)((k0) + bk1) * ND);          \
    } while (0)

    float acc[4][4][4];
#pragma unroll
    for (int mt = 0; mt < 4; mt++)
#pragma unroll
        for (int nt = 0; nt < 4; nt++)
#pragma unroll
            for (int i = 0; i < 4; i++) acc[mt][nt][i] = 0.f;

    const int NIT = KLEN / 16;
    LOAD_STAGE(0, 0);
    CP_COMMIT();

    for (int it = 0; it < NIT; it++) {
        const int s = it & 1;
        if (it + 1 < NIT) {
            LOAD_STAGE(s ^ 1, (it + 1) * 16);
            CP_COMMIT();
            CP_WAIT(1);
        } else {
            CP_WAIT(0);
        }
        __syncthreads();

#pragma unroll
        for (int kk = 0; kk < 2; kk++) {
            const int kb = kk * 8;
            uint32_t af[4][4];
#pragma unroll
            for (int mt = 0; mt < 4; mt++) {
                int rr = wr * 64 + mt * 16 + g;
                af[mt][0] = __float_as_uint(As[s][rr][kb + tg]);        // pre-rounded
                af[mt][1] = __float_as_uint(As[s][rr + 8][kb + tg]);
                af[mt][2] = __float_as_uint(As[s][rr][kb + tg + 4]);
                af[mt][3] = __float_as_uint(As[s][rr + 8][kb + tg + 4]);
            }
            uint32_t bf[4][2];
#pragma unroll
            for (int nt = 0; nt < 4; nt++) {
                int cc = wc * 32 + nt * 8 + g;
                bf[nt][0] = f2tf32(Bs[s][kb + tg][cc]);
                bf[nt][1] = f2tf32(Bs[s][kb + tg + 4][cc]);
            }
#pragma unroll
            for (int mt = 0; mt < 4; mt++)
#pragma unroll
                for (int nt = 0; nt < 4; nt++)
                    mma_tf32(acc[mt][nt], af[mt][0], af[mt][1], af[mt][2], af[mt][3],
                             bf[nt][0], bf[nt][1]);
        }
        __syncthreads();
    }
#undef LOAD_STAGE

    // ---- epilogue ----
#pragma unroll
    for (int mt = 0; mt < 4; mt++) {
        int rloc0 = m0 + wr * 64 + mt * 16 + g;
        int rloc1 = rloc0 + 8;
#pragma unroll
        for (int nt = 0; nt < 4; nt++) {
            int cc = n0 + wc * 32 + nt * 8 + tg * 2;
            if (MODE == 0) {
                if (rloc0 < cnt) {
                    float* p = g_h + (size_t)(e * CAP + rloc0) * ND + cc;
                    p[0] = __uint_as_float(f2tf32(gelu_exact(acc[mt][nt][0])));
                    p[1] = __uint_as_float(f2tf32(gelu_exact(acc[mt][nt][1])));
                }
                if (rloc1 < cnt) {
                    float* p = g_h + (size_t)(e * CAP + rloc1) * ND + cc;
                    p[0] = __uint_as_float(f2tf32(gelu_exact(acc[mt][nt][2])));
                    p[1] = __uint_as_float(f2tf32(gelu_exact(acc[mt][nt][3])));
                }
            } else {
                if (rloc0 < cnt) {
                    float* p = &g_ys[spl][(size_t)(e * CAP + rloc0) * ND + cc];
                    p[0] = acc[mt][nt][0];
                    p[1] = acc[mt][nt][1];
                }
                if (rloc1 < cnt) {
                    float* p = &g_ys[spl][(size_t)(e * CAP + rloc1) * ND + cc];
                    p[0] = acc[mt][nt][2];
                    p[1] = acc[mt][nt][3];
                }
            }
        }
    }
}

// ---------------------------------------------------------------
__global__ void combine_kernel(float* __restrict__ out) {
    int idx = blockIdx.x * blockDim.x + threadIdx.x;
    if (idx >= NTOK * H / 4) return;
    int elem = idx * 4;
    int n = elem / H;
    int h = elem % H;
    int r0 = g_slot_row[2 * n + 0];
    int r1 = g_slot_row[2 * n + 1];
    float gw0 = g_rw[r0], gw1 = g_rw[r1];

    float4 s0 = make_float4(0.f, 0.f, 0.f, 0.f);
    float4 s1 = make_float4(0.f, 0.f, 0.f, 0.f);
#pragma unroll
    for (int s = 0; s < NSPLIT; s++) {
        float4 a = *(const float4*)(&g_ys[s][0] + (size_t)r0 * H + h);
        float4 b = *(const float4*)(&g_ys[s][0] + (size_t)r1 * H + h);
        s0.x += a.x; s0.y += a.y; s0.z += a.z; s0.w += a.w;
        s1.x += b.x; s1.y += b.y; s1.z += b.z; s1.w += b.w;
    }
    float4 o;
    o.x = gw0 * s0.x + gw1 * s1.x;
    o.y = gw0 * s0.y + gw1 * s1.y;
    o.z = gw0 * s0.z + gw1 * s1.z;
    o.w = gw0 * s0.w + gw1 * s1.w;
    *(float4*)(out + elem) = o;
}

// ---------------------------------------------------------------
extern "C" void kernel_launch(void* const* d_in, const int* in_sizes, int n_in,
                              void* d_out, int out_size) {
    const float* x  = (const float*)d_in[0];
    const float* rw = (const float*)d_in[1];
    const float* w1 = (const float*)d_in[2];
    const float* w2 = (const float*)d_in[3];
    float* out = (float*)d_out;

    zero_cnt_kernel<<<1, 32>>>();
    router_kernel<<<NTOK / 8, 256>>>(x, rw);

    dim3 g1(F / 128, NTOK / 128, E);                 // (24, 8, 8)
    moe_mma_kernel<H, H, F, 0><<<g1, 256>>>(w1);

    dim3 g2(H / 128, NTOK / 128, E * NSPLIT);        // (6, 8, 24)
    moe_mma_kernel<F, KSPL, H, 1><<<g2, 256>>>(w2);

    combine_kernel<<<(NTOK * H / 4 + 255) / 256, 256>>>(out);
}

// round 9
// speedup vs baseline: 1.2027x; 1.0511x over previous
#include <cuda_runtime.h>
#include <cuda_fp16.h>
#include <math.h>
#include <stdint.h>

#define H    768
#define F    3072
#define E    8
#define NTOK 1024
#define CAP  1024
#define ROWS (E*CAP)
#define NSPLIT 3
#define KSPL (F / NSPLIT)   // 1024

#define W1P (E*(H/2)*F)     // packed half2 count for w1
#define W2P (E*(F/2)*H)

// ---- scratch (static device globals; no runtime allocation) ----
__device__ int      g_cnt[E];
__device__ int      g_tok[ROWS];
__device__ float    g_rw[ROWS];
__device__ int      g_slot_row[NTOK*2];
__device__ uint32_t g_xh[NTOK*(H/2)];            // x as packed half2 [tok][H/2]
__device__ uint32_t g_hh[(size_t)ROWS*(F/2)];    // gelu(x@w1) packed half2 [row][F/2]
__device__ uint32_t g_w1h[W1P];                  // w1 packed [e][H/2][F]
__device__ uint32_t g_w2h[W2P];                  // w2 packed [e][F/2][H]
__device__ float    g_ys[NSPLIT][(size_t)ROWS * H];

// ---------------------------------------------------------------
__device__ __forceinline__ uint32_t pack_h2(float a, float b) {
    __half2 h = __floats2half2_rn(a, b);
    return *(uint32_t*)&h;
}

__global__ void zero_cnt_kernel() {
    if (threadIdx.x < E) g_cnt[threadIdx.x] = 0;
}

// convert fp32 weights to packed half2 (pairs along K)
__global__ void convert_w_kernel(const float* __restrict__ w1,
                                 const float* __restrict__ w2) {
    size_t i = (size_t)blockIdx.x * blockDim.x + threadIdx.x;
    if (i < (size_t)W1P) {
        const int k2n = (H/2) * F;
        int e = (int)(i / k2n), r = (int)(i % k2n);
        int k2 = r / F, n = r % F;
        const float* p = w1 + ((size_t)e * H + 2 * k2) * F + n;
        g_w1h[i] = pack_h2(p[0], p[F]);
    } else if (i < (size_t)W1P + (size_t)W2P) {
        size_t j = i - W1P;
        const int k2n = (F/2) * H;
        int e = (int)(j / k2n), r = (int)(j % k2n);
        int k2 = r / H, n = r % H;
        const float* p = w2 + ((size_t)e * F + 2 * k2) * H + n;
        g_w2h[j] = pack_h2(p[0], p[H]);
    }
}

// router + x fp16 packing fused (1 warp per token)
__global__ void router_kernel(const float* __restrict__ x,
                              const float* __restrict__ rw) {
    int warp = (blockIdx.x * blockDim.x + threadIdx.x) >> 5;
    int lane = threadIdx.x & 31;
    if (warp >= NTOK) return;
    const float* xr = x + warp * H;

    // pack this token's row into g_xh
    {
        const float4* src = (const float4*)xr;
        uint32_t* dst = g_xh + warp * (H/2);
#pragma unroll
        for (int i = lane; i < H / 4; i += 32) {
            float4 v = src[i];
            dst[2*i]   = pack_h2(v.x, v.y);
            dst[2*i+1] = pack_h2(v.z, v.w);
        }
    }

    float acc[E];
#pragma unroll
    for (int e = 0; e < E; e++) acc[e] = 0.f;
    for (int k = lane; k < H; k += 32) {
        float xv = xr[k];
        const float* r = rw + k * E;
#pragma unroll
        for (int e = 0; e < E; e++) acc[e] += xv * r[e];
    }
#pragma unroll
    for (int e = 0; e < E; e++) {
#pragma unroll
        for (int o = 16; o > 0; o >>= 1)
            acc[e] += __shfl_down_sync(0xffffffffu, acc[e], o);
    }
    if (lane == 0) {
        float b0 = -INFINITY, b1 = -INFINITY;
        int i0 = 0, i1 = 0;
#pragma unroll
        for (int e = 0; e < E; e++) {
            float v = acc[e];
            if (v > b0) { b1 = b0; i1 = i0; b0 = v; i0 = e; }
            else if (v > b1) { b1 = v; i1 = e; }
        }
        float s  = expf(b1 - b0);
        float w0 = 1.f / (1.f + s);
        float w1v = s / (1.f + s);

        int p0 = atomicAdd(&g_cnt[i0], 1);
        int r0 = i0 * CAP + p0;
        g_tok[r0] = warp; g_rw[r0] = w0; g_slot_row[warp * 2 + 0] = r0;

        int p1 = atomicAdd(&g_cnt[i1], 1);
        int r1 = i1 * CAP + p1;
        g_tok[r1] = warp; g_rw[r1] = w1v; g_slot_row[warp * 2 + 1] = r1;
    }
}

__device__ __forceinline__ float gelu_exact(float v) {
    return 0.5f * v * (1.0f + erff(v * 0.70710678118654752f));
}

__device__ __forceinline__ void mma_f16(float c[4],
                                        uint32_t a0, uint32_t a1, uint32_t a2, uint32_t a3,
                                        uint32_t b0, uint32_t b1) {
    asm volatile(
        "mma.sync.aligned.m16n8k16.row.col.f32.f16.f16.f32 "
        "{%0,%1,%2,%3},{%4,%5,%6,%7},{%8,%9},{%0,%1,%2,%3};"
        : "+f"(c[0]), "+f"(c[1]), "+f"(c[2]), "+f"(c[3])
        : "r"(a0), "r"(a1), "r"(a2), "r"(a3), "r"(b0), "r"(b1));
}

#define CP_ASYNC16(dst, src) \
    asm volatile("cp.async.cg.shared.global [%0], [%1], 16;" :: "r"(dst), "l"(src))
#define CP_COMMIT() asm volatile("cp.async.commit_group;")
#define CP_WAIT(n)  asm volatile("cp.async.wait_group %0;" :: "n"(n))

// ---------------------------------------------------------------
// fp16 MMA FFN GEMM (R4-proven cp.async schedule, BK=32 f16 = 16 half2).
// MODE 0: g_hh = h2(gelu(g_xh[gather] @ w1h))  KSTR=768,  KLEN=768,  ND=3072
// MODE 1: g_ys[spl] = g_hh @ w2h[kslice]       KSTR=3072, KLEN=1024, ND=768
// 128x128 tile, 8 warps (2x4), warp 64x32 via m16n8k16.
template<int KSTR, int KLEN, int ND, int MODE>
__global__ void __launch_bounds__(256, 2)
moe_mma_kernel() {
    int e, spl;
    if (MODE == 0) { e = blockIdx.z; spl = 0; }
    else           { e = blockIdx.z / NSPLIT; spl = blockIdx.z % NSPLIT; }
    const int cnt = g_cnt[e];
    const int m0  = blockIdx.y * 128;
    if (m0 >= cnt) return;
    const int n0    = blockIdx.x * 128;
    const int kbeg2 = spl * (KLEN / 2);      // in half2 units

    __shared__ uint32_t As[2][128][20];   // [m][k2], 16 used + pad4
    __shared__ uint32_t Bs[2][16][136];   // [k2][n], 128 used + pad8

    const int t    = threadIdx.x;
    const int warp = t >> 5, lane = t & 31;
    const int wr = warp >> 2, wc = warp & 3;
    const int g  = lane >> 2, tg = lane & 3;

    // ---- A loader: thread t -> row t>>1, two 16B chunks at (t&1)*8 (+4) half2 ----
    const int am = t >> 1;
    const int ac = (t & 1) * 8;
    const uint32_t* arow;
    if (MODE == 0) {
        int tok = (m0 + am < cnt) ? g_tok[e * CAP + m0 + am] : 0;
        arow = g_xh + (size_t)tok * (KSTR/2);
    } else {
        int rr = e * CAP + ((m0 + am < cnt) ? m0 + am : 0);
        arow = g_hh + (size_t)rr * (KSTR/2) + kbeg2;
    }
    // ---- B loader: thread t -> k2-row t>>4, two chunks at (t&15)*8 (+4) ----
    const int bk = t >> 4;
    const int bc = (t & 15) * 8;
    const uint32_t* wh = (MODE == 0) ? g_w1h : g_w2h;
    const uint32_t* bptr = wh + ((size_t)e * (KSTR/2) + kbeg2 + bk) * ND + n0 + bc;

    uint32_t dA0[2], dA1[2], dB0[2], dB1[2];
#pragma unroll
    for (int s = 0; s < 2; s++) {
        dA0[s] = (uint32_t)__cvta_generic_to_shared(&As[s][am][ac]);
        dA1[s] = dA0[s] + 16;
        dB0[s] = (uint32_t)__cvta_generic_to_shared(&Bs[s][bk][bc]);
        dB1[s] = dB0[s] + 16;
    }

#define LOAD_STAGE(s, it2)                                             \
    do {                                                               \
        CP_ASYNC16(dA0[s], arow + (it2) * 16 + ac);                    \
        CP_ASYNC16(dA1[s], arow + (it2) * 16 + ac + 4);                \
        CP_ASYNC16(dB0[s], bptr + (size_t)(it2) * 16 * ND);            \
        CP_ASYNC16(dB1[s], bptr + (size_t)(it2) * 16 * ND + 4);        \
    } while (0)

    float acc[4][4][4];
#pragma unroll
    for (int mt = 0; mt < 4; mt++)
#pragma unroll
        for (int nt = 0; nt < 4; nt++)
#pragma unroll
            for (int i = 0; i < 4; i++) acc[mt][nt][i] = 0.f;

    const int NIT = KLEN / 32;      // BK = 32 f16
    LOAD_STAGE(0, 0);
    CP_COMMIT();

    for (int it = 0; it < NIT; it++) {
        const int s = it & 1;
        if (it + 1 < NIT) {
            LOAD_STAGE(s ^ 1, it + 1);
            CP_COMMIT();
            CP_WAIT(1);
        } else {
            CP_WAIT(0);
        }
        __syncthreads();

#pragma unroll
        for (int kk = 0; kk < 2; kk++) {
            const int kb2 = kk * 8;
            uint32_t af[4][4];
#pragma unroll
            for (int mt = 0; mt < 4; mt++) {
                int rr = wr * 64 + mt * 16 + g;
                af[mt][0] = As[s][rr][kb2 + tg];
                af[mt][1] = As[s][rr + 8][kb2 + tg];
                af[mt][2] = As[s][rr][kb2 + tg + 4];
                af[mt][3] = As[s][rr + 8][kb2 + tg + 4];
            }
            uint32_t bf[4][2];
#pragma unroll
            for (int nt = 0; nt < 4; nt++) {
                int cc = wc * 32 + nt * 8 + g;
                bf[nt][0] = Bs[s][kb2 + tg][cc];
                bf[nt][1] = Bs[s][kb2 + tg + 4][cc];
            }
#pragma unroll
            for (int mt = 0; mt < 4; mt++)
#pragma unroll
                for (int nt = 0; nt < 4; nt++)
                    mma_f16(acc[mt][nt], af[mt][0], af[mt][1], af[mt][2], af[mt][3],
                            bf[nt][0], bf[nt][1]);
        }
        __syncthreads();
    }
#undef LOAD_STAGE

    // ---- epilogue ----
#pragma unroll
    for (int mt = 0; mt < 4; mt++) {
        int rloc0 = m0 + wr * 64 + mt * 16 + g;
        int rloc1 = rloc0 + 8;
#pragma unroll
        for (int nt = 0; nt < 4; nt++) {
            if (MODE == 0) {
                // packed half2 column index
                int pc = (n0 >> 1) + wc * 16 + nt * 4 + tg;
                if (rloc0 < cnt) {
                    g_hh[(size_t)(e * CAP + rloc0) * (ND/2) + pc] =
                        pack_h2(gelu_exact(acc[mt][nt][0]), gelu_exact(acc[mt][nt][1]));
                }
                if (rloc1 < cnt) {
                    g_hh[(size_t)(e * CAP + rloc1) * (ND/2) + pc] =
                        pack_h2(gelu_exact(acc[mt][nt][2]), gelu_exact(acc[mt][nt][3]));
                }
            } else {
                int cc = n0 + wc * 32 + nt * 8 + tg * 2;
                if (rloc0 < cnt) {
                    float* p = &g_ys[spl][(size_t)(e * CAP + rloc0) * ND + cc];
                    p[0] = acc[mt][nt][0];
                    p[1] = acc[mt][nt][1];
                }
                if (rloc1 < cnt) {
                    float* p = &g_ys[spl][(size_t)(e * CAP + rloc1) * ND + cc];
                    p[0] = acc[mt][nt][2];
                    p[1] = acc[mt][nt][3];
                }
            }
        }
    }
}

// ---------------------------------------------------------------
__global__ void combine_kernel(float* __restrict__ out) {
    int idx = blockIdx.x * blockDim.x + threadIdx.x;
    if (idx >= NTOK * H / 4) return;
    int elem = idx * 4;
    int n = elem / H;
    int h = elem % H;
    int r0 = g_slot_row[2 * n + 0];
    int r1 = g_slot_row[2 * n + 1];
    float gw0 = g_rw[r0], gw1 = g_rw[r1];

    float4 s0 = make_float4(0.f, 0.f, 0.f, 0.f);
    float4 s1 = make_float4(0.f, 0.f, 0.f, 0.f);
#pragma unroll
    for (int s = 0; s < NSPLIT; s++) {
        float4 a = *(const float4*)(&g_ys[s][0] + (size_t)r0 * H + h);
        float4 b = *(const float4*)(&g_ys[s][0] + (size_t)r1 * H + h);
        s0.x += a.x; s0.y += a.y; s0.z += a.z; s0.w += a.w;
        s1.x += b.x; s1.y += b.y; s1.z += b.z; s1.w += b.w;
    }
    float4 o;
    o.x = gw0 * s0.x + gw1 * s1.x;
    o.y = gw0 * s0.y + gw1 * s1.y;
    o.z = gw0 * s0.z + gw1 * s1.z;
    o.w = gw0 * s0.w + gw1 * s1.w;
    *(float4*)(out + elem) = o;
}

// ---------------------------------------------------------------
extern "C" void kernel_launch(void* const* d_in, const int* in_sizes, int n_in,
                              void* d_out, int out_size) {
    const float* x  = (const float*)d_in[0];
    const float* rw = (const float*)d_in[1];
    const float* w1 = (const float*)d_in[2];
    const float* w2 = (const float*)d_in[3];
    float* out = (float*)d_out;

    zero_cnt_kernel<<<1, 32>>>();
    router_kernel<<<NTOK / 8, 256>>>(x, rw);

    size_t wtot = (size_t)W1P + (size_t)W2P;
    convert_w_kernel<<<(unsigned)((wtot + 255) / 256), 256>>>(w1, w2);

    dim3 g1(F / 128, NTOK / 128, E);                 // (24, 8, 8)
    moe_mma_kernel<H, H, F, 0><<<g1, 256>>>();

    dim3 g2(H / 128, NTOK / 128, E * NSPLIT);        // (6, 8, 24)
    moe_mma_kernel<F, KSPL, H, 1><<<g2, 256>>>();

    combine_kernel<<<(NTOK * H / 4 + 255) / 256, 256>>>(out);
}

// round 10
// speedup vs baseline: 1.3646x; 1.1346x over previous
#include <cuda_runtime.h>
#include <cuda_fp16.h>
#include <math.h>
#include <stdint.h>

#define H    768
#define F    3072
#define E    8
#define NTOK 1024
#define CAP  1024
#define ROWS (E*CAP)
#define NSPLIT 3
#define KSPL (F / NSPLIT)   // 1024

// smem stage sizes (bytes)
#define ASTG 10240          // 128 rows x 20 words x 4B
#define BSTG 8704           // 32 rows x 136 halfs x 2B
#define SB_B (3*ASTG)       // B region starts after 3 A stages
#define SMEM_BYTES (3*ASTG + 3*BSTG)   // 56832

// ---- scratch (static device globals; no runtime allocation) ----
__device__ int      g_cnt[E];
__device__ int      g_tok[ROWS];
__device__ float    g_rw[ROWS];
__device__ int      g_slot_row[NTOK*2];
__device__ uint32_t g_xh[NTOK*(H/2)];            // x packed half2 along k
__device__ uint32_t g_hh[(size_t)ROWS*(F/2)];    // gelu(x@w1) packed half2 along k
__device__ __half   g_w1h[(size_t)E*H*F];        // w1 plain half [e][k][n]
__device__ __half   g_w2h[(size_t)E*F*H];        // w2 plain half [e][k][n]
__device__ float    g_ys[NSPLIT][(size_t)ROWS * H];

// ---------------------------------------------------------------
__device__ __forceinline__ uint32_t pack_h2(float a, float b) {
    __half2 h = __floats2half2_rn(a, b);
    return *(uint32_t*)&h;
}

__global__ void zero_cnt_kernel() {
    if (threadIdx.x < E) g_cnt[threadIdx.x] = 0;
}

// linear fp32 -> fp16 stream for both weights (layout preserved)
__global__ void convert_w_kernel(const float* __restrict__ w1,
                                 const float* __restrict__ w2) {
    size_t i = (size_t)blockIdx.x * blockDim.x + threadIdx.x;   // 8 elems each
    const size_t n1 = (size_t)E * H * F / 8;
    const size_t n2 = (size_t)E * F * H / 8;
    const float* src;
    __half* dst;
    size_t j;
    if (i < n1)           { src = w1; dst = g_w1h; j = i; }
    else if (i < n1 + n2) { src = w2; dst = g_w2h; j = i - n1; }
    else return;
    float4 a = ((const float4*)src)[2*j];
    float4 b = ((const float4*)src)[2*j+1];
    uint4 o;
    o.x = pack_h2(a.x, a.y); o.y = pack_h2(a.z, a.w);
    o.z = pack_h2(b.x, b.y); o.w = pack_h2(b.z, b.w);
    ((uint4*)dst)[j] = o;
}

// router + x fp16 packing fused (1 warp per token)
__global__ void router_kernel(const float* __restrict__ x,
                              const float* __restrict__ rw) {
    int warp = (blockIdx.x * blockDim.x + threadIdx.x) >> 5;
    int lane = threadIdx.x & 31;
    if (warp >= NTOK) return;
    const float* xr = x + warp * H;
    {
        const float4* src = (const float4*)xr;
        uint32_t* dst = g_xh + warp * (H/2);
#pragma unroll
        for (int i = lane; i < H / 4; i += 32) {
            float4 v = src[i];
            dst[2*i]   = pack_h2(v.x, v.y);
            dst[2*i+1] = pack_h2(v.z, v.w);
        }
    }
    float acc[E];
#pragma unroll
    for (int e = 0; e < E; e++) acc[e] = 0.f;
    for (int k = lane; k < H; k += 32) {
        float xv = xr[k];
        const float* r = rw + k * E;
#pragma unroll
        for (int e = 0; e < E; e++) acc[e] += xv * r[e];
    }
#pragma unroll
    for (int e = 0; e < E; e++) {
#pragma unroll
        for (int o = 16; o > 0; o >>= 1)
            acc[e] += __shfl_down_sync(0xffffffffu, acc[e], o);
    }
    if (lane == 0) {
        float b0 = -INFINITY, b1 = -INFINITY;
        int i0 = 0, i1 = 0;
#pragma unroll
        for (int e = 0; e < E; e++) {
            float v = acc[e];
            if (v > b0) { b1 = b0; i1 = i0; b0 = v; i0 = e; }
            else if (v > b1) { b1 = v; i1 = e; }
        }
        float s  = expf(b1 - b0);
        float w0 = 1.f / (1.f + s);
        float w1v = s / (1.f + s);
        int p0 = atomicAdd(&g_cnt[i0], 1);
        int r0 = i0 * CAP + p0;
        g_tok[r0] = warp; g_rw[r0] = w0; g_slot_row[warp * 2 + 0] = r0;
        int p1 = atomicAdd(&g_cnt[i1], 1);
        int r1 = i1 * CAP + p1;
        g_tok[r1] = warp; g_rw[r1] = w1v; g_slot_row[warp * 2 + 1] = r1;
    }
}

__device__ __forceinline__ float gelu_exact(float v) {
    return 0.5f * v * (1.0f + erff(v * 0.70710678118654752f));
}

__device__ __forceinline__ void mma_f16(float c[4],
                                        uint32_t a0, uint32_t a1, uint32_t a2, uint32_t a3,
                                        uint32_t b0, uint32_t b1) {
    asm volatile(
        "mma.sync.aligned.m16n8k16.row.col.f32.f16.f16.f32 "
        "{%0,%1,%2,%3},{%4,%5,%6,%7},{%8,%9},{%0,%1,%2,%3};"
        : "+f"(c[0]), "+f"(c[1]), "+f"(c[2]), "+f"(c[3])
        : "r"(a0), "r"(a1), "r"(a2), "r"(a3), "r"(b0), "r"(b1));
}
__device__ __forceinline__ void ldm_x4(uint32_t& r0, uint32_t& r1, uint32_t& r2, uint32_t& r3,
                                       uint32_t addr) {
    asm volatile("ldmatrix.sync.aligned.m8n8.x4.shared.b16 {%0,%1,%2,%3}, [%4];"
        : "=r"(r0), "=r"(r1), "=r"(r2), "=r"(r3) : "r"(addr));
}
__device__ __forceinline__ void ldm_x4t(uint32_t& r0, uint32_t& r1, uint32_t& r2, uint32_t& r3,
                                        uint32_t addr) {
    asm volatile("ldmatrix.sync.aligned.m8n8.x4.trans.shared.b16 {%0,%1,%2,%3}, [%4];"
        : "=r"(r0), "=r"(r1), "=r"(r2), "=r"(r3) : "r"(addr));
}

#define CP_ASYNC16(dst, src) \
    asm volatile("cp.async.cg.shared.global [%0], [%1], 16;" :: "r"(dst), "l"(src))
#define CP_COMMIT() asm volatile("cp.async.commit_group;")
#define CP_WAIT1()  asm volatile("cp.async.wait_group 1;")
#define CP_WAIT0()  asm volatile("cp.async.wait_group 0;")

// ---------------------------------------------------------------
// fp16 MMA FFN GEMM. 3-stage, 2-iteration prefetch cover, 1 barrier/iter,
// ldmatrix fragments. 128x128 tile, BK=32 f16, 8 warps (2x4), warp 64x32.
// MODE 0: g_hh = h2(gelu(g_xh[gather] @ w1h))  KSTR=768,  KLEN=768,  ND=3072
// MODE 1: g_ys[spl] = g_hh @ w2h[kslice]       KSTR=3072, KLEN=1024, ND=768
template<int KSTR, int KLEN, int ND, int MODE>
__global__ void __launch_bounds__(256, 2)
moe_mma_kernel() {
    int e, spl;
    if (MODE == 0) { e = blockIdx.z; spl = 0; }
    else           { e = blockIdx.z / NSPLIT; spl = blockIdx.z % NSPLIT; }
    const int cnt = g_cnt[e];
    const int m0  = blockIdx.y * 128;
    if (m0 >= cnt) return;
    const int n0   = blockIdx.x * 128;
    const int kbeg = spl * KLEN;

    extern __shared__ char smem[];
    const uint32_t sb = (uint32_t)__cvta_generic_to_shared(smem);

    const int t    = threadIdx.x;
    const int warp = t >> 5, lane = t & 31;
    const int wr = warp >> 2, wc = warp & 3;
    const int g  = lane >> 2, tg = lane & 3;

    // ---- A loader: thread t -> row t>>1, word chunks (t&1)*8 + {0,4} ----
    const int am = t >> 1;
    const int ac = (t & 1) * 8;
    const uint32_t* arow;
    if (MODE == 0) {
        int tok = (m0 + am < cnt) ? g_tok[e * CAP + m0 + am] : 0;
        arow = g_xh + (size_t)tok * (KSTR/2);
    } else {
        int rr = e * CAP + ((m0 + am < cnt) ? m0 + am : 0);
        arow = g_hh + (size_t)rr * (KSTR/2) + (kbeg/2);
    }
    const uint32_t dA = sb + am * 80 + ac * 4;       // + s*ASTG, +16 for 2nd chunk

    // ---- B loader: thread t -> k-row t>>3 (0..31), half col (t&7)*16 ----
    const int bk = t >> 3;
    const int bc = (t & 7) * 16;
    const __half* wh = (MODE == 0) ? g_w1h : g_w2h;
    const __half* bptr = wh + ((size_t)e * KSTR + kbeg + bk) * ND + n0 + bc;
    const uint32_t dB = sb + SB_B + bk * 272 + bc * 2;   // + s*BSTG, +16

#define LOAD_STAGE(s, it2)                                             \
    do {                                                               \
        const uint32_t* asrc = arow + (size_t)(it2) * 16 + ac;         \
        CP_ASYNC16(dA + (s) * ASTG, asrc);                             \
        CP_ASYNC16(dA + (s) * ASTG + 16, asrc + 4);                    \
        const __half* bsrc = bptr + (size_t)(it2) * 32 * ND;           \
        CP_ASYNC16(dB + (s) * BSTG, bsrc);                             \
        CP_ASYNC16(dB + (s) * BSTG + 16, bsrc + 8);                    \
        CP_COMMIT();                                                   \
    } while (0)

    // ---- fragment ldmatrix base addresses ----
    const uint32_t aFrag = sb + (wr * 64 + (lane & 15)) * 80 + (lane >> 4) * 16;
    const uint32_t bFrag = sb + SB_B + (lane & 15) * 272 + wc * 64 + (lane >> 4) * 16;

    float acc[4][4][4];
#pragma unroll
    for (int mt = 0; mt < 4; mt++)
#pragma unroll
        for (int nt = 0; nt < 4; nt++)
#pragma unroll
            for (int i = 0; i < 4; i++) acc[mt][nt][i] = 0.f;

    const int NIT = KLEN / 32;
    LOAD_STAGE(0, 0);
    LOAD_STAGE(1, 1);

    int s = 0;
    for (int it = 0; it < NIT; it++) {
        if (it + 1 < NIT) CP_WAIT1(); else CP_WAIT0();
        __syncthreads();
        if (it + 2 < NIT) {
            int sn = s + 2; if (sn >= 3) sn -= 3;
            LOAD_STAGE(sn, it + 2);
        }

#pragma unroll
        for (int kk = 0; kk < 2; kk++) {
            uint32_t af[4][4];
#pragma unroll
            for (int mt = 0; mt < 4; mt++)
                ldm_x4(af[mt][0], af[mt][1], af[mt][2], af[mt][3],
                       aFrag + s * ASTG + kk * 32 + mt * 1280);
            uint32_t bf[2][4];
#pragma unroll
            for (int ntp = 0; ntp < 2; ntp++)
                ldm_x4t(bf[ntp][0], bf[ntp][1], bf[ntp][2], bf[ntp][3],
                        bFrag + s * BSTG + kk * 4352 + ntp * 32);
#pragma unroll
            for (int mt = 0; mt < 4; mt++)
#pragma unroll
                for (int nt = 0; nt < 4; nt++)
                    mma_f16(acc[mt][nt], af[mt][0], af[mt][1], af[mt][2], af[mt][3],
                            bf[nt >> 1][(nt & 1) * 2], bf[nt >> 1][(nt & 1) * 2 + 1]);
        }
        s++; if (s >= 3) s -= 3;
    }
#undef LOAD_STAGE

    // ---- epilogue ----
#pragma unroll
    for (int mt = 0; mt < 4; mt++) {
        int rloc0 = m0 + wr * 64 + mt * 16 + g;
        int rloc1 = rloc0 + 8;
#pragma unroll
        for (int nt = 0; nt < 4; nt++) {
            if (MODE == 0) {
                int pc = (n0 >> 1) + wc * 16 + nt * 4 + tg;   // packed half2 col
                if (rloc0 < cnt)
                    g_hh[(size_t)(e * CAP + rloc0) * (ND/2) + pc] =
                        pack_h2(gelu_exact(acc[mt][nt][0]), gelu_exact(acc[mt][nt][1]));
                if (rloc1 < cnt)
                    g_hh[(size_t)(e * CAP + rloc1) * (ND/2) + pc] =
                        pack_h2(gelu_exact(acc[mt][nt][2]), gelu_exact(acc[mt][nt][3]));
            } else {
                int cc = n0 + wc * 32 + nt * 8 + tg * 2;
                if (rloc0 < cnt) {
                    float* p = &g_ys[spl][(size_t)(e * CAP + rloc0) * ND + cc];
                    p[0] = acc[mt][nt][0];
                    p[1] = acc[mt][nt][1];
                }
                if (rloc1 < cnt) {
                    float* p = &g_ys[spl][(size_t)(e * CAP + rloc1) * ND + cc];
                    p[0] = acc[mt][nt][2];
                    p[1] = acc[mt][nt][3];
                }
            }
        }
    }
}

// ---------------------------------------------------------------
__global__ void combine_kernel(float* __restrict__ out) {
    int idx = blockIdx.x * blockDim.x + threadIdx.x;
    if (idx >= NTOK * H / 4) return;
    int elem = idx * 4;
    int n = elem / H;
    int h = elem % H;
    int r0 = g_slot_row[2 * n + 0];
    int r1 = g_slot_row[2 * n + 1];
    float gw0 = g_rw[r0], gw1 = g_rw[r1];

    float4 s0 = make_float4(0.f, 0.f, 0.f, 0.f);
    float4 s1 = make_float4(0.f, 0.f, 0.f, 0.f);
#pragma unroll
    for (int s = 0; s < NSPLIT; s++) {
        float4 a = *(const float4*)(&g_ys[s][0] + (size_t)r0 * H + h);
        float4 b = *(const float4*)(&g_ys[s][0] + (size_t)r1 * H + h);
        s0.x += a.x; s0.y += a.y; s0.z += a.z; s0.w += a.w;
        s1.x += b.x; s1.y += b.y; s1.z += b.z; s1.w += b.w;
    }
    float4 o;
    o.x = gw0 * s0.x + gw1 * s1.x;
    o.y = gw0 * s0.y + gw1 * s1.y;
    o.z = gw0 * s0.z + gw1 * s1.z;
    o.w = gw0 * s0.w + gw1 * s1.w;
    *(float4*)(out + elem) = o;
}

// ---------------------------------------------------------------
extern "C" void kernel_launch(void* const* d_in, const int* in_sizes, int n_in,
                              void* d_out, int out_size) {
    const float* x  = (const float*)d_in[0];
    const float* rw = (const float*)d_in[1];
    const float* w1 = (const float*)d_in[2];
    const float* w2 = (const float*)d_in[3];
    float* out = (float*)d_out;

    cudaFuncSetAttribute(moe_mma_kernel<H, H, F, 0>,
                         cudaFuncAttributeMaxDynamicSharedMemorySize, SMEM_BYTES);
    cudaFuncSetAttribute(moe_mma_kernel<F, KSPL, H, 1>,
                         cudaFuncAttributeMaxDynamicSharedMemorySize, SMEM_BYTES);

    zero_cnt_kernel<<<1, 32>>>();
    router_kernel<<<NTOK / 8, 256>>>(x, rw);

    size_t wtot = ((size_t)E * H * F + (size_t)E * F * H) / 8;
    convert_w_kernel<<<(unsigned)((wtot + 255) / 256), 256>>>(w1, w2);

    dim3 g1(F / 128, NTOK / 128, E);                 // (24, 8, 8)
    moe_mma_kernel<H, H, F, 0><<<g1, 256, SMEM_BYTES>>>();

    dim3 g2(H / 128, NTOK / 128, E * NSPLIT);        // (6, 8, 24)
    moe_mma_kernel<F, KSPL, H, 1><<<g2, 256, SMEM_BYTES>>>();

    combine_kernel<<<(NTOK * H / 4 + 255) / 256, 256>>>(out);
}

// round 11
// speedup vs baseline: 1.3752x; 1.0078x over previous
#include <cuda_runtime.h>
#include <cuda_fp16.h>
#include <math.h>
#include <stdint.h>

#define H    768
#define F    3072
#define E    8
#define NTOK 1024
#define CAP  1024
#define ROWS (E*CAP)
#define NSPLIT 3
#define KSPL (F / NSPLIT)   // 1024

#define NSTG 5
// smem stage sizes (bytes)
#define ASTG 10240          // 128 rows x 20 words x 4B
#define BSTG 8704           // 32 rows x 136 halfs x 2B
#define SB_B (NSTG*ASTG)    // B region starts after A stages
#define SMEM_BYTES (NSTG*(ASTG+BSTG))   // 94720

// ---- scratch (static device globals; no runtime allocation) ----
__device__ int      g_cnt[E];
__device__ int      g_tok[ROWS];
__device__ float    g_rw[ROWS];
__device__ int      g_slot_row[NTOK*2];
__device__ uint32_t g_xh[NTOK*(H/2)];            // x packed half2 along k
__device__ uint32_t g_hh[(size_t)ROWS*(F/2)];    // gelu(x@w1) packed half2 along k
__device__ __half   g_w1h[(size_t)E*H*F];        // w1 plain half [e][k][n]
__device__ __half   g_w2h[(size_t)E*F*H];        // w2 plain half [e][k][n]
__device__ float    g_ys[NSPLIT][(size_t)ROWS * H];

// ---------------------------------------------------------------
__device__ __forceinline__ uint32_t pack_h2(float a, float b) {
    __half2 h = __floats2half2_rn(a, b);
    return *(uint32_t*)&h;
}

__global__ void zero_cnt_kernel() {
    if (threadIdx.x < E) g_cnt[threadIdx.x] = 0;
}

// linear fp32 -> fp16 stream for both weights (layout preserved)
__global__ void convert_w_kernel(const float* __restrict__ w1,
                                 const float* __restrict__ w2) {
    size_t i = (size_t)blockIdx.x * blockDim.x + threadIdx.x;   // 8 elems each
    const size_t n1 = (size_t)E * H * F / 8;
    const size_t n2 = (size_t)E * F * H / 8;
    const float* src;
    __half* dst;
    size_t j;
    if (i < n1)           { src = w1; dst = g_w1h; j = i; }
    else if (i < n1 + n2) { src = w2; dst = g_w2h; j = i - n1; }
    else return;
    float4 a = ((const float4*)src)[2*j];
    float4 b = ((const float4*)src)[2*j+1];
    uint4 o;
    o.x = pack_h2(a.x, a.y); o.y = pack_h2(a.z, a.w);
    o.z = pack_h2(b.x, b.y); o.w = pack_h2(b.z, b.w);
    ((uint4*)dst)[j] = o;
}

// router + x fp16 packing fused (1 warp per token)
__global__ void router_kernel(const float* __restrict__ x,
                              const float* __restrict__ rw) {
    int warp = (blockIdx.x * blockDim.x + threadIdx.x) >> 5;
    int lane = threadIdx.x & 31;
    if (warp >= NTOK) return;
    const float* xr = x + warp * H;
    {
        const float4* src = (const float4*)xr;
        uint32_t* dst = g_xh + warp * (H/2);
#pragma unroll
        for (int i = lane; i < H / 4; i += 32) {
            float4 v = src[i];
            dst[2*i]   = pack_h2(v.x, v.y);
            dst[2*i+1] = pack_h2(v.z, v.w);
        }
    }
    float acc[E];
#pragma unroll
    for (int e = 0; e < E; e++) acc[e] = 0.f;
    for (int k = lane; k < H; k += 32) {
        float xv = xr[k];
        const float* r = rw + k * E;
#pragma unroll
        for (int e = 0; e < E; e++) acc[e] += xv * r[e];
    }
#pragma unroll
    for (int e = 0; e < E; e++) {
#pragma unroll
        for (int o = 16; o > 0; o >>= 1)
            acc[e] += __shfl_down_sync(0xffffffffu, acc[e], o);
    }
    if (lane == 0) {
        float b0 = -INFINITY, b1 = -INFINITY;
        int i0 = 0, i1 = 0;
#pragma unroll
        for (int e = 0; e < E; e++) {
            float v = acc[e];
            if (v > b0) { b1 = b0; i1 = i0; b0 = v; i0 = e; }
            else if (v > b1) { b1 = v; i1 = e; }
        }
        float s  = expf(b1 - b0);
        float w0 = 1.f / (1.f + s);
        float w1v = s / (1.f + s);
        int p0 = atomicAdd(&g_cnt[i0], 1);
        int r0 = i0 * CAP + p0;
        g_tok[r0] = warp; g_rw[r0] = w0; g_slot_row[warp * 2 + 0] = r0;
        int p1 = atomicAdd(&g_cnt[i1], 1);
        int r1 = i1 * CAP + p1;
        g_tok[r1] = warp; g_rw[r1] = w1v; g_slot_row[warp * 2 + 1] = r1;
    }
}

__device__ __forceinline__ float gelu_exact(float v) {
    return 0.5f * v * (1.0f + erff(v * 0.70710678118654752f));
}

__device__ __forceinline__ void mma_f16(float c[4],
                                        uint32_t a0, uint32_t a1, uint32_t a2, uint32_t a3,
                                        uint32_t b0, uint32_t b1) {
    asm volatile(
        "mma.sync.aligned.m16n8k16.row.col.f32.f16.f16.f32 "
        "{%0,%1,%2,%3},{%4,%5,%6,%7},{%8,%9},{%0,%1,%2,%3};"
        : "+f"(c[0]), "+f"(c[1]), "+f"(c[2]), "+f"(c[3])
        : "r"(a0), "r"(a1), "r"(a2), "r"(a3), "r"(b0), "r"(b1));
}
__device__ __forceinline__ void ldm_x4(uint32_t& r0, uint32_t& r1, uint32_t& r2, uint32_t& r3,
                                       uint32_t addr) {
    asm volatile("ldmatrix.sync.aligned.m8n8.x4.shared.b16 {%0,%1,%2,%3}, [%4];"
        : "=r"(r0), "=r"(r1), "=r"(r2), "=r"(r3) : "r"(addr));
}
__device__ __forceinline__ void ldm_x4t(uint32_t& r0, uint32_t& r1, uint32_t& r2, uint32_t& r3,
                                        uint32_t addr) {
    asm volatile("ldmatrix.sync.aligned.m8n8.x4.trans.shared.b16 {%0,%1,%2,%3}, [%4];"
        : "=r"(r0), "=r"(r1), "=r"(r2), "=r"(r3) : "r"(addr));
}

#define CP_ASYNC16(dst, src) \
    asm volatile("cp.async.cg.shared.global [%0], [%1], 16;" :: "r"(dst), "l"(src))
#define CP_COMMIT() asm volatile("cp.async.commit_group;")
#define CP_WAIT(n)  asm volatile("cp.async.wait_group %0;" :: "n"(n))

// ---------------------------------------------------------------
// fp16 MMA FFN GEMM. 5-stage, depth-4 prefetch, 1 barrier/iter, ldmatrix.
// 128x128 tile, BK=32 f16, 8 warps (2x4), warp 64x32 via m16n8k16.
// MODE 0: g_hh = h2(gelu(g_xh[gather] @ w1h))  KSTR=768,  KLEN=768,  ND=3072
// MODE 1: g_ys[spl] = g_hh @ w2h[kslice]       KSTR=3072, KLEN=1024, ND=768
template<int KSTR, int KLEN, int ND, int MODE>
__global__ void __launch_bounds__(256, 2)
moe_mma_kernel() {
    int e, spl;
    if (MODE == 0) { e = blockIdx.z; spl = 0; }
    else           { e = blockIdx.z / NSPLIT; spl = blockIdx.z % NSPLIT; }
    const int cnt = g_cnt[e];
    const int m0  = blockIdx.y * 128;
    if (m0 >= cnt) return;
    const int n0   = blockIdx.x * 128;
    const int kbeg = spl * KLEN;

    extern __shared__ char smem[];
    const uint32_t sb = (uint32_t)__cvta_generic_to_shared(smem);

    const int t    = threadIdx.x;
    const int warp = t >> 5, lane = t & 31;
    const int wr = warp >> 2, wc = warp & 3;
    const int g  = lane >> 2, tg = lane & 3;

    // ---- A loader: thread t -> row t>>1, word chunks (t&1)*8 + {0,4} ----
    const int am = t >> 1;
    const int ac = (t & 1) * 8;
    const uint32_t* arow;
    if (MODE == 0) {
        int tok = (m0 + am < cnt) ? g_tok[e * CAP + m0 + am] : 0;
        arow = g_xh + (size_t)tok * (KSTR/2);
    } else {
        int rr = e * CAP + ((m0 + am < cnt) ? m0 + am : 0);
        arow = g_hh + (size_t)rr * (KSTR/2) + (kbeg/2);
    }
    const uint32_t dA = sb + am * 80 + ac * 4;

    // ---- B loader: thread t -> k-row t>>3 (0..31), half col (t&7)*16 ----
    const int bk = t >> 3;
    const int bc = (t & 7) * 16;
    const __half* wh = (MODE == 0) ? g_w1h : g_w2h;
    const __half* bptr = wh + ((size_t)e * KSTR + kbeg + bk) * ND + n0 + bc;
    const uint32_t dB = sb + SB_B + bk * 272 + bc * 2;

#define LOAD_STAGE(s, it2)                                             \
    do {                                                               \
        const uint32_t* asrc = arow + (size_t)(it2) * 16 + ac;         \
        CP_ASYNC16(dA + (s) * ASTG, asrc);                             \
        CP_ASYNC16(dA + (s) * ASTG + 16, asrc + 4);                    \
        const __half* bsrc = bptr + (size_t)(it2) * 32 * ND;           \
        CP_ASYNC16(dB + (s) * BSTG, bsrc);                             \
        CP_ASYNC16(dB + (s) * BSTG + 16, bsrc + 8);                    \
        CP_COMMIT();                                                   \
    } while (0)

    // ---- fragment ldmatrix base addresses ----
    const uint32_t aFrag = sb + (wr * 64 + (lane & 15)) * 80 + (lane >> 4) * 16;
    const uint32_t bFrag = sb + SB_B + (lane & 15) * 272 + wc * 64 + (lane >> 4) * 16;

    float acc[4][4][4];
#pragma unroll
    for (int mt = 0; mt < 4; mt++)
#pragma unroll
        for (int nt = 0; nt < 4; nt++)
#pragma unroll
            for (int i = 0; i < 4; i++) acc[mt][nt][i] = 0.f;

    const int NIT = KLEN / 32;   // 24 or 32 (>= NSTG-1)
    LOAD_STAGE(0, 0);
    LOAD_STAGE(1, 1);
    LOAD_STAGE(2, 2);
    LOAD_STAGE(3, 3);

    int s = 0;
    for (int it = 0; it < NIT; it++) {
        // exact wait: group(it) must be complete; outstanding-after = min(3, NIT-1-it)
        const int rem = NIT - 1 - it;
        if (rem >= 3)      CP_WAIT(3);
        else if (rem == 2) CP_WAIT(2);
        else if (rem == 1) CP_WAIT(1);
        else               CP_WAIT(0);
        __syncthreads();
        if (it + 4 < NIT) {
            int sn = s + 4; if (sn >= NSTG) sn -= NSTG;
            LOAD_STAGE(sn, it + 4);
        }

#pragma unroll
        for (int kk = 0; kk < 2; kk++) {
            uint32_t af[4][4];
#pragma unroll
            for (int mt = 0; mt < 4; mt++)
                ldm_x4(af[mt][0], af[mt][1], af[mt][2], af[mt][3],
                       aFrag + s * ASTG + kk * 32 + mt * 1280);
            uint32_t bf[2][4];
#pragma unroll
            for (int ntp = 0; ntp < 2; ntp++)
                ldm_x4t(bf[ntp][0], bf[ntp][1], bf[ntp][2], bf[ntp][3],
                        bFrag + s * BSTG + kk * 4352 + ntp * 32);
#pragma unroll
            for (int mt = 0; mt < 4; mt++)
#pragma unroll
                for (int nt = 0; nt < 4; nt++)
                    mma_f16(acc[mt][nt], af[mt][0], af[mt][1], af[mt][2], af[mt][3],
                            bf[nt >> 1][(nt & 1) * 2], bf[nt >> 1][(nt & 1) * 2 + 1]);
        }
        s++; if (s >= NSTG) s -= NSTG;
    }
#undef LOAD_STAGE

    // ---- epilogue ----
#pragma unroll
    for (int mt = 0; mt < 4; mt++) {
        int rloc0 = m0 + wr * 64 + mt * 16 + g;
        int rloc1 = rloc0 + 8;
#pragma unroll
        for (int nt = 0; nt < 4; nt++) {
            if (MODE == 0) {
                int pc = (n0 >> 1) + wc * 16 + nt * 4 + tg;   // packed half2 col
                if (rloc0 < cnt)
                    g_hh[(size_t)(e * CAP + rloc0) * (ND/2) + pc] =
                        pack_h2(gelu_exact(acc[mt][nt][0]), gelu_exact(acc[mt][nt][1]));
                if (rloc1 < cnt)
                    g_hh[(size_t)(e * CAP + rloc1) * (ND/2) + pc] =
                        pack_h2(gelu_exact(acc[mt][nt][2]), gelu_exact(acc[mt][nt][3]));
            } else {
                int cc = n0 + wc * 32 + nt * 8 + tg * 2;
                if (rloc0 < cnt) {
                    float* p = &g_ys[spl][(size_t)(e * CAP + rloc0) * ND + cc];
                    p[0] = acc[mt][nt][0];
                    p[1] = acc[mt][nt][1];
                }
                if (rloc1 < cnt) {
                    float* p = &g_ys[spl][(size_t)(e * CAP + rloc1) * ND + cc];
                    p[0] = acc[mt][nt][2];
                    p[1] = acc[mt][nt][3];
                }
            }
        }
    }
}

// ---------------------------------------------------------------
__global__ void combine_kernel(float* __restrict__ out) {
    int idx = blockIdx.x * blockDim.x + threadIdx.x;
    if (idx >= NTOK * H / 4) return;
    int elem = idx * 4;
    int n = elem / H;
    int h = elem % H;
    int r0 = g_slot_row[2 * n + 0];
    int r1 = g_slot_row[2 * n + 1];
    float gw0 = g_rw[r0], gw1 = g_rw[r1];

    float4 s0 = make_float4(0.f, 0.f, 0.f, 0.f);
    float4 s1 = make_float4(0.f, 0.f, 0.f, 0.f);
#pragma unroll
    for (int s = 0; s < NSPLIT; s++) {
        float4 a = *(const float4*)(&g_ys[s][0] + (size_t)r0 * H + h);
        float4 b = *(const float4*)(&g_ys[s][0] + (size_t)r1 * H + h);
        s0.x += a.x; s0.y += a.y; s0.z += a.z; s0.w += a.w;
        s1.x += b.x; s1.y += b.y; s1.z += b.z; s1.w += b.w;
    }
    float4 o;
    o.x = gw0 * s0.x + gw1 * s1.x;
    o.y = gw0 * s0.y + gw1 * s1.y;
    o.z = gw0 * s0.z + gw1 * s1.z;
    o.w = gw0 * s0.w + gw1 * s1.w;
    *(float4*)(out + elem) = o;
}

// ---------------------------------------------------------------
extern "C" void kernel_launch(void* const* d_in, const int* in_sizes, int n_in,
                              void* d_out, int out_size) {
    const float* x  = (const float*)d_in[0];
    const float* rw = (const float*)d_in[1];
    const float* w1 = (const float*)d_in[2];
    const float* w2 = (const float*)d_in[3];
    float* out = (float*)d_out;

    cudaFuncSetAttribute(moe_mma_kernel<H, H, F, 0>,
                         cudaFuncAttributeMaxDynamicSharedMemorySize, SMEM_BYTES);
    cudaFuncSetAttribute(moe_mma_kernel<F, KSPL, H, 1>,
                         cudaFuncAttributeMaxDynamicSharedMemorySize, SMEM_BYTES);

    zero_cnt_kernel<<<1, 32>>>();
    router_kernel<<<NTOK / 8, 256>>>(x, rw);

    size_t wtot = ((size_t)E * H * F + (size_t)E * F * H) / 8;
    convert_w_kernel<<<(unsigned)((wtot + 255) / 256), 256>>>(w1, w2);

    dim3 g1(F / 128, NTOK / 128, E);                 // (24, 8, 8)
    moe_mma_kernel<H, H, F, 0><<<g1, 256, SMEM_BYTES>>>();

    dim3 g2(H / 128, NTOK / 128, E * NSPLIT);        // (6, 8, 24)
    moe_mma_kernel<F, KSPL, H, 1><<<g2, 256, SMEM_BYTES>>>();

    combine_kernel<<<(NTOK * H / 4 + 255) / 256, 256>>>(out);
}